// round 13
// baseline (speedup 1.0000x reference)
#include <cuda_runtime.h>
#include <cuda_fp16.h>
#include <stdint.h>

// out[m] = x[m]·W + b + 0.5*||x[m]V||^2 - 0.5*(sum_i x[m,i])^2 * ||V.sum(0)||^2
// x: (16384,4096) f32, W: (1,4096) f32, b: (1,) f32, V: (4096,128) f32, out f32.
// GEMM fp16 x fp16 -> fp16 acc (V pre-scaled 4096); side sums exact fp32.
// Grid 147 x 112 rows. Batched LDSM->MMA. 4-stage smem, 1 barrier per 2 chunks.

#define MROWS 16384
#define KDIM  4096
#define NDIM  128
#define KC    64
#define NCH   (KDIM / KC)          // 64
#define NSTRIP 7                   // m16 strips per CTA (112 rows)
#define CTAROWS 112
#define GRID  147
#define AROW  144                  // padded smem row stride (bytes)
#define ABUF  (CTAROWS * AROW)     // 16128
#define BBUF  (128 * AROW)         // 18432

#define OF_B   (4 * ABUF)                 // 64512
#define OF_RED (OF_B + 4 * BBUF)          // 138240
#define OF_SXS (OF_RED + CTAROWS * 8 * 4) // 141824
#define OF_SWS (OF_SXS + CTAROWS * 4)     // 142272
#define SMEM_TOTAL (OF_SWS + CTAROWS * 4) // 142720

#define VSCALE 4096.0f
#define T1SCALE (0.5f / (VSCALE * VSCALE))

__device__ __half g_Vt[(size_t)NCH * NDIM * KC];   // chunk-major [c][n][kk], fp16 of 4096*V^T
__device__ float g_spart[256 * NDIM];
__device__ float g_s2;

// ---------------- helpers ----------------

static __device__ __forceinline__ uint32_t smem_u32(const void* p) {
    uint32_t r;
    asm("{ .reg .u64 t; cvta.to.shared.u64 t, %1; cvt.u32.u64 %0, t; }"
        : "=r"(r) : "l"(p));
    return r;
}

static __device__ __forceinline__ uint32_t pack2h(float lo, float hi) {
    __half2 h = __floats2half2_rn(lo, hi);
    return *reinterpret_cast<uint32_t*>(&h);
}

#define MMA_F16(d0, d1, a0, a1, a2, a3, b0, b1)                            \
    asm volatile(                                                          \
        "mma.sync.aligned.m16n8k16.row.col.f16.f16.f16.f16 "               \
        "{%0,%1}, {%2,%3,%4,%5}, {%6,%7}, {%0,%1};"                        \
        : "+r"(d0), "+r"(d1)                                               \
        : "r"(a0), "r"(a1), "r"(a2), "r"(a3), "r"(b0), "r"(b1))

#define LDSM_X4(r0, r1, r2, r3, addr)                                      \
    asm volatile("ldmatrix.sync.aligned.m8n8.x4.shared.b16 "               \
                 "{%0,%1,%2,%3}, [%4];"                                    \
                 : "=r"(r0), "=r"(r1), "=r"(r2), "=r"(r3) : "r"(addr))

// ---------------- prep kernels ----------------

// 256 blocks, block b handles 16 K-rows: k in [16b, 16b+16). 48B smem rows.
__global__ void prep_kernel(const float* __restrict__ V) {
    __shared__ __align__(16) __half sm[128 * 24];
    __shared__ float ps[256];
    const int t = threadIdx.x;
    const int b = blockIdx.x;
    const int k0 = b * 16;
    const int n = t & 127;
    const int half_ = t >> 7;

    float partial = 0.f;
#pragma unroll
    for (int i = 0; i < 8; i++) {
        int kk = 2 * i + half_;
        float v = V[(size_t)(k0 + kk) * NDIM + n];
        partial += v;
        sm[n * 24 + kk] = __float2half_rn(v * VSCALE);
    }
    ps[t] = partial;
    __syncthreads();
    if (t < 128) g_spart[b * 128 + t] = ps[t] + ps[t + 128];

    const int r = t >> 1, part = t & 1;
    const uint4* src = (const uint4*)((const char*)sm + r * 48 + part * 16);
    uint4 u0 = src[0];
    uint4* dst = (uint4*)((char*)g_Vt + (size_t)(b >> 2) * 16384 + r * 128
                          + (b & 3) * 32 + part * 16);
    dst[0] = u0;
}

__global__ void s2_kernel() {
    __shared__ float sh[256];
    __shared__ float sq[128];
    const int t = threadIdx.x;      // 256 threads
    const int n = t & 127, part = t >> 7;
    float s = 0.f;
    for (int b2 = part * 128; b2 < part * 128 + 128; b2++)
        s += g_spart[b2 * 128 + n];
    sh[t] = s;
    __syncthreads();
    if (t < 128) {
        const float tot = sh[t] + sh[t + 128];
        sq[t] = tot * tot;
    }
    __syncthreads();
    for (int o = 64; o > 0; o >>= 1) {
        if (t < o) sq[t] += sq[t + o];
        __syncthreads();
    }
    if (t == 0) g_s2 = sq[0];
}

// ---------------- main kernel ----------------
// 256 thr = 8 warps; warp w owns n-slice [16w,16w+16) over all 7 m16 strips.
// Per k-step: batch 1 B-LDSM + 7 A-LDSM, then 14 independent MMAs.
// 4 smem stages; producers at distance 2; one __syncthreads per 2 chunks.

__global__ void __launch_bounds__(256, 1) fm_main(
    const float* __restrict__ x, const float* __restrict__ W,
    const float* __restrict__ bias, float* __restrict__ out)
{
    extern __shared__ __align__(16) char smem[];
    float (*red)[8] = (float(*)[8])(smem + OF_RED);
    float* sxs = (float*)(smem + OF_SXS);
    float* sws = (float*)(smem + OF_SWS);

    const int t = threadIdx.x;
    const int wid = t >> 5, lane = t & 31;
    int mbase = blockIdx.x * CTAROWS;
    if (mbase > MROWS - CTAROWS) mbase = MROWS - CTAROWS;  // tail overlap (dup writes identical)

    const uint32_t sAu = smem_u32(smem);
    const uint32_t sBu = sAu + OF_B;

    // ---- gmem pointers: single A base, strip offsets compile-time consts
    const char* xb = (const char*)x + ((size_t)(mbase + (t >> 4)) << 14) + (t & 15) * 16;
    const char* vb = (const char*)g_Vt + (size_t)t * 16;
    const float4* wp = (const float4*)W + (t & 15);

    // ---- STS addresses
    const uint32_t asts = sAu + (t >> 4) * AROW + (t & 15) * 8;
    const uint32_t bsts = sBu + (t >> 3) * AROW + (t & 7) * 16;

    // ---- ldmatrix addresses
    const uint32_t alds = sAu + (uint32_t)(lane & 15) * AROW + (lane >> 4) * 16;
    const uint32_t blds = sBu + (uint32_t)(wid * 16 + (lane >> 4) * 8 + (lane & 7)) * AROW
                        + ((lane >> 3) & 1) * 16;

    // fp16 packed accumulators: acc[strip][nt] = {c0c1, c2c3}
    uint32_t acc[NSTRIP][2][2];
#pragma unroll
    for (int s = 0; s < NSTRIP; s++)
#pragma unroll
        for (int j = 0; j < 2; j++) { acc[s][j][0] = 0u; acc[s][j][1] = 0u; }

    float sx[NSTRIP], sw[NSTRIP];
#pragma unroll
    for (int i = 0; i < NSTRIP; i++) { sx[i] = 0.f; sw[i] = 0.f; }

    float4 areg[NSTRIP];
    uint4  breg[4];

#define LOADA(c) do {                                                       \
        _Pragma("unroll")                                                   \
        for (int i = 0; i < NSTRIP; i++)                                    \
            areg[i] = *(const float4*)(xb + ((size_t)i << 18) + (c) * 256); \
    } while (0)

#define LOADB(c) do {                                                       \
        _Pragma("unroll")                                                   \
        for (int j = 0; j < 4; j++)                                         \
            breg[j] = *(const uint4*)(vb + (size_t)(c) * 16384 + j * 4096); \
    } while (0)

#define SUMS_STS(c, buf) do {                                               \
        const float4 w4 = wp[(c) * 16];                                     \
        const uint32_t aof_ = (uint32_t)(buf) * ABUF;                       \
        const uint32_t bof_ = (uint32_t)(buf) * BBUF;                       \
        _Pragma("unroll")                                                   \
        for (int i = 0; i < NSTRIP; i++) {                                  \
            const float4 q = areg[i];                                       \
            sx[i] += (q.x + q.y) + (q.z + q.w);                             \
            sw[i] += q.x * w4.x + q.y * w4.y + q.z * w4.z + q.w * w4.w;     \
            const uint32_t p0 = pack2h(q.x, q.y), p1 = pack2h(q.z, q.w);    \
            asm volatile("st.shared.v2.b32 [%0], {%1,%2};"                  \
                         :: "r"(asts + aof_ + i * (16 * AROW)), "r"(p0), "r"(p1)); \
        }                                                                   \
        _Pragma("unroll")                                                   \
        for (int j = 0; j < 4; j++)                                         \
            asm volatile("st.shared.v4.b32 [%0], {%1,%2,%3,%4};"            \
                         :: "r"(bsts + bof_ + j * (32 * AROW)), "r"(breg[j].x), \
                            "r"(breg[j].y), "r"(breg[j].z), "r"(breg[j].w));\
    } while (0)

    // one chunk of MMAs from smem stage `buf`
#define MMA_CHUNK(buf) do {                                                 \
        const uint32_t aof = (uint32_t)(buf) * ABUF;                        \
        const uint32_t bof = (uint32_t)(buf) * BBUF;                        \
        _Pragma("unroll")                                                   \
        for (int ks = 0; ks < 4; ks++) {                                    \
            uint32_t bfr[4];                                                \
            LDSM_X4(bfr[0], bfr[1], bfr[2], bfr[3], blds + bof + ks * 32);  \
            uint32_t afr[NSTRIP][4];                                        \
            _Pragma("unroll")                                               \
            for (int s = 0; s < NSTRIP; s++)                                \
                LDSM_X4(afr[s][0], afr[s][1], afr[s][2], afr[s][3],         \
                        alds + aof + ks * 32 + s * (16 * AROW));            \
            _Pragma("unroll")                                               \
            for (int s = 0; s < NSTRIP; s++) {                              \
                MMA_F16(acc[s][0][0], acc[s][0][1],                         \
                        afr[s][0], afr[s][1], afr[s][2], afr[s][3],         \
                        bfr[0], bfr[1]);                                    \
                MMA_F16(acc[s][1][0], acc[s][1][1],                         \
                        afr[s][0], afr[s][1], afr[s][2], afr[s][3],         \
                        bfr[2], bfr[3]);                                    \
            }                                                               \
        }                                                                   \
    } while (0)

    // prologue: stage chunks 0 and 1
    LOADA(0); LOADB(0);
    SUMS_STS(0, 0);
    LOADA(1); LOADB(1);
    SUMS_STS(1, 1);
    __syncthreads();

#pragma unroll 1
    for (int cc = 0; cc < NCH; cc += 2) {
        const bool more = (cc + 2 < NCH);
        if (more) { LOADA(cc + 2); LOADB(cc + 2); }   // LDGs in flight over chunk cc

        MMA_CHUNK(cc & 3);

        if (more) {
            SUMS_STS(cc + 2, (cc + 2) & 3);           // mid-pair: tensor drains chunk cc
            LOADA(cc + 3); LOADB(cc + 3);
        }

        MMA_CHUNK((cc + 1) & 3);

        if (more) SUMS_STS(cc + 3, (cc + 3) & 3);     // only exposed tail per pair
        __syncthreads();
    }

    // ---------------- epilogue ----------------
#pragma unroll
    for (int s = 0; s < NSTRIP; s++) {
        float p0 = 0.f, p1 = 0.f;
#pragma unroll
        for (int nt = 0; nt < 2; nt++) {
            const float2 f0 = __half22float2(*reinterpret_cast<__half2*>(&acc[s][nt][0]));
            const float2 f1 = __half22float2(*reinterpret_cast<__half2*>(&acc[s][nt][1]));
            p0 += f0.x * f0.x + f0.y * f0.y;
            p1 += f1.x * f1.x + f1.y * f1.y;
        }
        p0 += __shfl_xor_sync(0xffffffffu, p0, 1);
        p0 += __shfl_xor_sync(0xffffffffu, p0, 2);
        p1 += __shfl_xor_sync(0xffffffffu, p1, 1);
        p1 += __shfl_xor_sync(0xffffffffu, p1, 2);
        if ((lane & 3) == 0) {
            red[s * 16 + (lane >> 2)][wid]     = p0;
            red[s * 16 + 8 + (lane >> 2)][wid] = p1;
        }
    }

#pragma unroll
    for (int i = 0; i < NSTRIP; i++) {
#pragma unroll
        for (int o = 8; o > 0; o >>= 1) {
            sx[i] += __shfl_xor_sync(0xffffffffu, sx[i], o);
            sw[i] += __shfl_xor_sync(0xffffffffu, sw[i], o);
        }
    }
    if ((t & 15) == 0) {
        const int h = t >> 4;
#pragma unroll
        for (int i = 0; i < NSTRIP; i++) {
            sxs[i * 16 + h] = sx[i];
            sws[i * 16 + h] = sw[i];
        }
    }
    __syncthreads();

    if (t < CTAROWS) {
        float t1 = 0.f;
#pragma unroll
        for (int w = 0; w < 8; w++) t1 += red[t][w];
        const float s_ = sxs[t];
        out[mbase + t] = sws[t] + bias[0] + T1SCALE * t1 - 0.5f * s_ * s_ * g_s2;
    }
}

// ---------------- launch ----------------

extern "C" void kernel_launch(void* const* d_in, const int* in_sizes, int n_in,
                              void* d_out, int out_size) {
    (void)in_sizes; (void)n_in; (void)out_size;
    const float* x = (const float*)d_in[0];
    const float* W = (const float*)d_in[1];
    const float* b = (const float*)d_in[2];
    const float* V = (const float*)d_in[3];
    float* out = (float*)d_out;

    cudaFuncSetAttribute(fm_main, cudaFuncAttributeMaxDynamicSharedMemorySize, SMEM_TOTAL);

    prep_kernel<<<256, 256>>>(V);
    s2_kernel<<<1, 256>>>();
    fm_main<<<GRID, 256, SMEM_TOTAL>>>(x, W, b, out);
}

// round 14
// speedup vs baseline: 1.0208x; 1.0208x over previous
#include <cuda_runtime.h>
#include <cuda_fp16.h>
#include <stdint.h>

// out[m] = x[m]·W + b + 0.5*||x[m]V||^2 - 0.5*(sum_i x[m,i])^2 * ||V.sum(0)||^2
// x: (16384,4096) f32, W: (1,4096) f32, b: (1,) f32, V: (4096,128) f32, out f32.
// GEMM fp16 (V pre-scaled 4096), f16 acc; side sums exact fp32.
// SPLIT-K: grid 294 = 147 row-blocks x 2 K-halves, 2 CTAs/SM for phase overlap.
// Partial xv stored f16 (lossless from acc) to gmem slabs; combine kernel
// adds halves in fp32, squares, writes out. No atomics -> deterministic.

#define MROWS 16384
#define KDIM  4096
#define NDIM  128
#define KC    64
#define NCHH  32                   // chunks per K-half
#define NSTRIP 7
#define CTAROWS 112
#define GRID  294
#define AROW  144                  // padded smem row stride (bytes)
#define ABUF  (CTAROWS * AROW)     // 16128
#define BBUF  (128 * AROW)         // 18432
#define SMEM_TOTAL (2 * ABUF + 2 * BBUF)   // 69120 -> 2 CTAs = 138240 < 227KB

#define VSCALE 4096.0f
#define T1SCALE (0.5f / (VSCALE * VSCALE))

__device__ __half g_Vt[(size_t)64 * NDIM * KC];    // chunk-major [c][n][kk], fp16 of 4096*V^T
__device__ float g_spart[256 * NDIM];
__device__ float g_s2;
__device__ uint32_t g_xv[2][(size_t)MROWS * 64];   // f16x2 col-pairs, per K-half
__device__ float g_sxp[2][MROWS];                  // xsum halves
__device__ float g_swp[2][MROWS];                  // xW halves

// ---------------- helpers ----------------

static __device__ __forceinline__ uint32_t smem_u32(const void* p) {
    uint32_t r;
    asm("{ .reg .u64 t; cvta.to.shared.u64 t, %1; cvt.u32.u64 %0, t; }"
        : "=r"(r) : "l"(p));
    return r;
}

static __device__ __forceinline__ uint32_t pack2h(float lo, float hi) {
    __half2 h = __floats2half2_rn(lo, hi);
    return *reinterpret_cast<uint32_t*>(&h);
}

#define MMA_F16(d0, d1, a0, a1, a2, a3, b0, b1)                            \
    asm volatile(                                                          \
        "mma.sync.aligned.m16n8k16.row.col.f16.f16.f16.f16 "               \
        "{%0,%1}, {%2,%3,%4,%5}, {%6,%7}, {%0,%1};"                        \
        : "+r"(d0), "+r"(d1)                                               \
        : "r"(a0), "r"(a1), "r"(a2), "r"(a3), "r"(b0), "r"(b1))

#define LDSM_X4(r0, r1, r2, r3, addr)                                      \
    asm volatile("ldmatrix.sync.aligned.m8n8.x4.shared.b16 "               \
                 "{%0,%1,%2,%3}, [%4];"                                    \
                 : "=r"(r0), "=r"(r1), "=r"(r2), "=r"(r3) : "r"(addr))

// ---------------- prep kernels ----------------

__global__ void prep_kernel(const float* __restrict__ V) {
    __shared__ __align__(16) __half sm[128 * 24];
    __shared__ float ps[256];
    const int t = threadIdx.x;
    const int b = blockIdx.x;
    const int k0 = b * 16;
    const int n = t & 127;
    const int half_ = t >> 7;

    float partial = 0.f;
#pragma unroll
    for (int i = 0; i < 8; i++) {
        int kk = 2 * i + half_;
        float v = V[(size_t)(k0 + kk) * NDIM + n];
        partial += v;
        sm[n * 24 + kk] = __float2half_rn(v * VSCALE);
    }
    ps[t] = partial;
    __syncthreads();
    if (t < 128) g_spart[b * 128 + t] = ps[t] + ps[t + 128];

    const int r = t >> 1, part = t & 1;
    const uint4* src = (const uint4*)((const char*)sm + r * 48 + part * 16);
    uint4 u0 = src[0];
    uint4* dst = (uint4*)((char*)g_Vt + (size_t)(b >> 2) * 16384 + r * 128
                          + (b & 3) * 32 + part * 16);
    dst[0] = u0;
}

__global__ void s2_kernel() {
    __shared__ float sh[256];
    __shared__ float sq[128];
    const int t = threadIdx.x;
    const int n = t & 127, part = t >> 7;
    float s = 0.f;
    for (int b2 = part * 128; b2 < part * 128 + 128; b2++)
        s += g_spart[b2 * 128 + n];
    sh[t] = s;
    __syncthreads();
    if (t < 128) {
        const float tot = sh[t] + sh[t + 128];
        sq[t] = tot * tot;
    }
    __syncthreads();
    for (int o = 64; o > 0; o >>= 1) {
        if (t < o) sq[t] += sq[t + o];
        __syncthreads();
    }
    if (t == 0) g_s2 = sq[0];
}

// ---------------- main kernel (split-K half) ----------------
// blockIdx = rb*2 + kh. CTA: 112 rows x 128 cols x K 2048 (32 chunks).
// Round-12 layout: 8 warps n16 over 7 strips; batched LDSM -> 14 MMAs.

__global__ void __launch_bounds__(256, 2) fm_main(
    const float* __restrict__ x, const float* __restrict__ W)
{
    extern __shared__ __align__(16) char smem[];

    const int t = threadIdx.x;
    const int wid = t >> 5, lane = t & 31;
    const int rb = blockIdx.x >> 1;
    const int kh = blockIdx.x & 1;
    int mbase = rb * CTAROWS;
    if (mbase > MROWS - CTAROWS) mbase = MROWS - CTAROWS;  // overlap; slab dup writes identical

    const uint32_t sAu = smem_u32(smem);
    const uint32_t sBu = sAu + 2 * ABUF;

    // ---- gmem pointers (K-half offset folded in)
    const char* xb = (const char*)x + ((size_t)(mbase + (t >> 4)) << 14)
                   + (size_t)kh * 8192 + (t & 15) * 16;
    const char* vb = (const char*)g_Vt + (size_t)kh * NCHH * 16384 + (size_t)t * 16;
    const float4* wp = (const float4*)W + kh * 512 + (t & 15);

    // ---- STS addresses
    const uint32_t asts = sAu + (t >> 4) * AROW + (t & 15) * 8;
    const uint32_t bsts = sBu + (t >> 3) * AROW + (t & 7) * 16;

    // ---- ldmatrix addresses
    const uint32_t alds = sAu + (uint32_t)(lane & 15) * AROW + (lane >> 4) * 16;
    const uint32_t blds = sBu + (uint32_t)(wid * 16 + (lane >> 4) * 8 + (lane & 7)) * AROW
                        + ((lane >> 3) & 1) * 16;

    uint32_t acc[NSTRIP][2][2];
#pragma unroll
    for (int s = 0; s < NSTRIP; s++)
#pragma unroll
        for (int j = 0; j < 2; j++) { acc[s][j][0] = 0u; acc[s][j][1] = 0u; }

    float sx[NSTRIP], sw[NSTRIP];
#pragma unroll
    for (int i = 0; i < NSTRIP; i++) { sx[i] = 0.f; sw[i] = 0.f; }

    float4 areg[NSTRIP];
    uint4  breg[4];

#define LOADA(c) do {                                                       \
        _Pragma("unroll")                                                   \
        for (int i = 0; i < NSTRIP; i++)                                    \
            areg[i] = *(const float4*)(xb + ((size_t)i << 18) + (c) * 256); \
    } while (0)

#define LOADB(c) do {                                                       \
        _Pragma("unroll")                                                   \
        for (int j = 0; j < 4; j++)                                         \
            breg[j] = *(const uint4*)(vb + (size_t)(c) * 16384 + j * 4096); \
    } while (0)

#define SUMS_STS(c, buf) do {                                               \
        const float4 w4 = wp[(c) * 16];                                     \
        const uint32_t aof_ = (uint32_t)(buf) * ABUF;                       \
        const uint32_t bof_ = (uint32_t)(buf) * BBUF;                       \
        _Pragma("unroll")                                                   \
        for (int i = 0; i < NSTRIP; i++) {                                  \
            const float4 q = areg[i];                                       \
            sx[i] += (q.x + q.y) + (q.z + q.w);                             \
            sw[i] += q.x * w4.x + q.y * w4.y + q.z * w4.z + q.w * w4.w;     \
            const uint32_t p0 = pack2h(q.x, q.y), p1 = pack2h(q.z, q.w);    \
            asm volatile("st.shared.v2.b32 [%0], {%1,%2};"                  \
                         :: "r"(asts + aof_ + i * (16 * AROW)), "r"(p0), "r"(p1)); \
        }                                                                   \
        _Pragma("unroll")                                                   \
        for (int j = 0; j < 4; j++)                                         \
            asm volatile("st.shared.v4.b32 [%0], {%1,%2,%3,%4};"            \
                         :: "r"(bsts + bof_ + j * (32 * AROW)), "r"(breg[j].x), \
                            "r"(breg[j].y), "r"(breg[j].z), "r"(breg[j].w));\
    } while (0)

    LOADA(0); LOADB(0);
    SUMS_STS(0, 0);
    __syncthreads();

#pragma unroll 1
    for (int c = 0; c < NCHH; c++) {
        const bool more = (c + 1 < NCHH);
        if (more) { LOADA(c + 1); LOADB(c + 1); }

        const uint32_t aof = (uint32_t)(c & 1) * ABUF;
        const uint32_t bof = (uint32_t)(c & 1) * BBUF;

#pragma unroll
        for (int ks = 0; ks < 4; ks++) {
            uint32_t bfr[4];
            LDSM_X4(bfr[0], bfr[1], bfr[2], bfr[3], blds + bof + ks * 32);
            uint32_t afr[NSTRIP][4];
#pragma unroll
            for (int s = 0; s < NSTRIP; s++)
                LDSM_X4(afr[s][0], afr[s][1], afr[s][2], afr[s][3],
                        alds + aof + ks * 32 + s * (16 * AROW));
#pragma unroll
            for (int s = 0; s < NSTRIP; s++) {
                MMA_F16(acc[s][0][0], acc[s][0][1],
                        afr[s][0], afr[s][1], afr[s][2], afr[s][3],
                        bfr[0], bfr[1]);
                MMA_F16(acc[s][1][0], acc[s][1][1],
                        afr[s][0], afr[s][1], afr[s][2], afr[s][3],
                        bfr[2], bfr[3]);
            }
        }

        if (more) SUMS_STS(c + 1, (c + 1) & 1);
        __syncthreads();
    }

    // ---------------- epilogue: store partials (no cross-warp reduce) ----------------
    // acc pair d0 = (row lq, colpair lr), d1 = (row lq+8, colpair lr) of warp's n16.
    {
        uint32_t* slab = g_xv[kh];
#pragma unroll
        for (int s = 0; s < NSTRIP; s++) {
            const int r0 = mbase + s * 16 + (lane >> 2);
#pragma unroll
            for (int nt = 0; nt < 2; nt++) {
                const int cp = wid * 8 + nt * 4 + (lane & 3);
                slab[(size_t)r0 * 64 + cp]       = acc[s][nt][0];
                slab[(size_t)(r0 + 8) * 64 + cp] = acc[s][nt][1];
            }
        }
    }

    // side sums: reduce over 16 threads sharing each row, store halves
#pragma unroll
    for (int i = 0; i < NSTRIP; i++) {
#pragma unroll
        for (int o = 8; o > 0; o >>= 1) {
            sx[i] += __shfl_xor_sync(0xffffffffu, sx[i], o);
            sw[i] += __shfl_xor_sync(0xffffffffu, sw[i], o);
        }
    }
    if ((t & 15) == 0) {
        const int h = t >> 4;
#pragma unroll
        for (int i = 0; i < NSTRIP; i++) {
            const int row = mbase + i * 16 + h;
            g_sxp[kh][row] = sx[i];
            g_swp[kh][row] = sw[i];
        }
    }
}

// ---------------- combine kernel ----------------
// 256 blocks x 256 thr; warp handles 8 rows. Adds K-half xv partials in fp32,
// squares, reduces, writes final out.
__global__ void combine_kernel(const float* __restrict__ bias,
                               float* __restrict__ out)
{
    const int w = threadIdx.x >> 5, lane = threadIdx.x & 31;
    const int rowbase = blockIdx.x * 64 + w * 8;
    const float s2 = g_s2;
    const float bb = bias[0];

#pragma unroll
    for (int rr = 0; rr < 8; rr++) {
        const int m = rowbase + rr;
        const uint32_t* p0 = &g_xv[0][(size_t)m * 64];
        const uint32_t* p1 = &g_xv[1][(size_t)m * 64];
        float accv = 0.f;
#pragma unroll
        for (int j = 0; j < 2; j++) {
            const uint32_t a = p0[lane + 32 * j];
            const uint32_t b = p1[lane + 32 * j];
            const float2 fa = __half22float2(*reinterpret_cast<const __half2*>(&a));
            const float2 fb = __half22float2(*reinterpret_cast<const __half2*>(&b));
            const float u = fa.x + fb.x, v = fa.y + fb.y;
            accv += u * u + v * v;
        }
#pragma unroll
        for (int o = 16; o > 0; o >>= 1)
            accv += __shfl_xor_sync(0xffffffffu, accv, o);
        if (lane == 0) {
            const float sxv = g_sxp[0][m] + g_sxp[1][m];
            const float swv = g_swp[0][m] + g_swp[1][m];
            out[m] = swv + bb + T1SCALE * accv - 0.5f * sxv * sxv * s2;
        }
    }
}

// ---------------- launch ----------------

extern "C" void kernel_launch(void* const* d_in, const int* in_sizes, int n_in,
                              void* d_out, int out_size) {
    (void)in_sizes; (void)n_in; (void)out_size;
    const float* x = (const float*)d_in[0];
    const float* W = (const float*)d_in[1];
    const float* b = (const float*)d_in[2];
    const float* V = (const float*)d_in[3];
    float* out = (float*)d_out;

    cudaFuncSetAttribute(fm_main, cudaFuncAttributeMaxDynamicSharedMemorySize, SMEM_TOTAL);

    prep_kernel<<<256, 256>>>(V);
    s2_kernel<<<1, 256>>>();
    fm_main<<<GRID, 256, SMEM_TOTAL>>>(x, W);
    combine_kernel<<<256, 256>>>(b, out);
}

// round 15
// speedup vs baseline: 1.0293x; 1.0084x over previous
#include <cuda_runtime.h>
#include <cuda_fp16.h>
#include <stdint.h>

// out[m] = x[m]·W + b + 0.5*||x[m]V||^2 - 0.5*(sum_i x[m,i])^2 * ||V.sum(0)||^2
// x: (16384,4096) f32, W: (1,4096) f32, b: (1,) f32, V: (4096,128) f32, out f32.
// GEMM fp16 (V pre-scaled 4096), f16 acc; side sums exact fp32.
// SPLIT-K: grid 294 = 147 row-blocks x 2 K-halves, 2 CTAs/SM for phase overlap.
// Partial xv stored f16 (lossless from acc); parallel combine adds halves in
// fp32, squares, writes out. No atomics -> deterministic.

#define MROWS 16384
#define KDIM  4096
#define NDIM  128
#define KC    64
#define NCHH  32                   // chunks per K-half
#define NSTRIP 7
#define CTAROWS 112
#define GRID  294
#define AROW  144                  // padded smem row stride (bytes)
#define ABUF  (CTAROWS * AROW)     // 16128
#define BBUF  (128 * AROW)         // 18432
#define SMEM_TOTAL (2 * ABUF + 2 * BBUF)   // 69120 -> 2 CTAs = 138240 < 227KB

#define VSCALE 4096.0f
#define T1SCALE (0.5f / (VSCALE * VSCALE))

__device__ __half g_Vt[(size_t)64 * NDIM * KC];    // chunk-major [c][n][kk], fp16 of 4096*V^T
__device__ float g_spart[256 * NDIM];
__device__ float g_sp2[16 * NDIM];
__device__ float g_s2;
__device__ uint32_t g_xv[2][(size_t)MROWS * 64];   // f16x2 col-pairs, per K-half
__device__ float g_sxp[2][MROWS];                  // xsum halves
__device__ float g_swp[2][MROWS];                  // xW halves

// ---------------- helpers ----------------

static __device__ __forceinline__ uint32_t smem_u32(const void* p) {
    uint32_t r;
    asm("{ .reg .u64 t; cvta.to.shared.u64 t, %1; cvt.u32.u64 %0, t; }"
        : "=r"(r) : "l"(p));
    return r;
}

static __device__ __forceinline__ uint32_t pack2h(float lo, float hi) {
    __half2 h = __floats2half2_rn(lo, hi);
    return *reinterpret_cast<uint32_t*>(&h);
}

#define MMA_F16(d0, d1, a0, a1, a2, a3, b0, b1)                            \
    asm volatile(                                                          \
        "mma.sync.aligned.m16n8k16.row.col.f16.f16.f16.f16 "               \
        "{%0,%1}, {%2,%3,%4,%5}, {%6,%7}, {%0,%1};"                        \
        : "+r"(d0), "+r"(d1)                                               \
        : "r"(a0), "r"(a1), "r"(a2), "r"(a3), "r"(b0), "r"(b1))

#define LDSM_X4(r0, r1, r2, r3, addr)                                      \
    asm volatile("ldmatrix.sync.aligned.m8n8.x4.shared.b16 "               \
                 "{%0,%1,%2,%3}, [%4];"                                    \
                 : "=r"(r0), "=r"(r1), "=r"(r2), "=r"(r3) : "r"(addr))

// ---------------- prep kernels ----------------

__global__ void prep_kernel(const float* __restrict__ V) {
    __shared__ __align__(16) __half sm[128 * 24];
    __shared__ float ps[256];
    const int t = threadIdx.x;
    const int b = blockIdx.x;
    const int k0 = b * 16;
    const int n = t & 127;
    const int half_ = t >> 7;

    float partial = 0.f;
#pragma unroll
    for (int i = 0; i < 8; i++) {
        int kk = 2 * i + half_;
        float v = V[(size_t)(k0 + kk) * NDIM + n];
        partial += v;
        sm[n * 24 + kk] = __float2half_rn(v * VSCALE);
    }
    ps[t] = partial;
    __syncthreads();
    if (t < 128) g_spart[b * 128 + t] = ps[t] + ps[t + 128];

    const int r = t >> 1, part = t & 1;
    const uint4* src = (const uint4*)((const char*)sm + r * 48 + part * 16);
    uint4 u0 = src[0];
    uint4* dst = (uint4*)((char*)g_Vt + (size_t)(b >> 2) * 16384 + r * 128
                          + (b & 3) * 32 + part * 16);
    dst[0] = u0;
}

// stage 1: 16 blocks, block bl reduces partial rows [16bl, 16bl+16)
__global__ void s2a_kernel() {
    __shared__ float sh[256];
    const int t = threadIdx.x;
    const int n = t & 127, part = t >> 7;
    const int b0 = blockIdx.x * 16 + part * 8;
    float s = 0.f;
#pragma unroll
    for (int j = 0; j < 8; j++) s += g_spart[(b0 + j) * 128 + n];
    sh[t] = s;
    __syncthreads();
    if (t < 128) g_sp2[blockIdx.x * 128 + t] = sh[t] + sh[t + 128];
}

// stage 2: final 16-way add per n, square, tree reduce
__global__ void s2b_kernel() {
    __shared__ float sq[128];
    const int t = threadIdx.x;   // 128 threads
    float s = 0.f;
#pragma unroll
    for (int j = 0; j < 16; j++) s += g_sp2[j * 128 + t];
    sq[t] = s * s;
    __syncthreads();
    for (int o = 64; o > 0; o >>= 1) {
        if (t < o) sq[t] += sq[t + o];
        __syncthreads();
    }
    if (t == 0) g_s2 = sq[0];
}

// ---------------- main kernel (split-K half) ----------------
// blockIdx = rb*2 + kh. CTA: 112 rows x 128 cols x K 2048 (32 chunks).
// 8 warps n16 over 7 strips; batched LDSM -> 14 MMAs. (round-14 proven)

__global__ void __launch_bounds__(256, 2) fm_main(
    const float* __restrict__ x, const float* __restrict__ W)
{
    extern __shared__ __align__(16) char smem[];

    const int t = threadIdx.x;
    const int wid = t >> 5, lane = t & 31;
    const int rb = blockIdx.x >> 1;
    const int kh = blockIdx.x & 1;
    int mbase = rb * CTAROWS;
    if (mbase > MROWS - CTAROWS) mbase = MROWS - CTAROWS;  // overlap; dup writes identical

    const uint32_t sAu = smem_u32(smem);
    const uint32_t sBu = sAu + 2 * ABUF;

    const char* xb = (const char*)x + ((size_t)(mbase + (t >> 4)) << 14)
                   + (size_t)kh * 8192 + (t & 15) * 16;
    const char* vb = (const char*)g_Vt + (size_t)kh * NCHH * 16384 + (size_t)t * 16;
    const float4* wp = (const float4*)W + kh * 512 + (t & 15);

    const uint32_t asts = sAu + (t >> 4) * AROW + (t & 15) * 8;
    const uint32_t bsts = sBu + (t >> 3) * AROW + (t & 7) * 16;

    const uint32_t alds = sAu + (uint32_t)(lane & 15) * AROW + (lane >> 4) * 16;
    const uint32_t blds = sBu + (uint32_t)(wid * 16 + (lane >> 4) * 8 + (lane & 7)) * AROW
                        + ((lane >> 3) & 1) * 16;

    uint32_t acc[NSTRIP][2][2];
#pragma unroll
    for (int s = 0; s < NSTRIP; s++)
#pragma unroll
        for (int j = 0; j < 2; j++) { acc[s][j][0] = 0u; acc[s][j][1] = 0u; }

    float sx[NSTRIP], sw[NSTRIP];
#pragma unroll
    for (int i = 0; i < NSTRIP; i++) { sx[i] = 0.f; sw[i] = 0.f; }

    float4 areg[NSTRIP];
    uint4  breg[4];

#define LOADA(c) do {                                                       \
        _Pragma("unroll")                                                   \
        for (int i = 0; i < NSTRIP; i++)                                    \
            areg[i] = *(const float4*)(xb + ((size_t)i << 18) + (c) * 256); \
    } while (0)

#define LOADB(c) do {                                                       \
        _Pragma("unroll")                                                   \
        for (int j = 0; j < 4; j++)                                         \
            breg[j] = *(const uint4*)(vb + (size_t)(c) * 16384 + j * 4096); \
    } while (0)

#define SUMS_STS(c, buf) do {                                               \
        const float4 w4 = wp[(c) * 16];                                     \
        const uint32_t aof_ = (uint32_t)(buf) * ABUF;                       \
        const uint32_t bof_ = (uint32_t)(buf) * BBUF;                       \
        _Pragma("unroll")                                                   \
        for (int i = 0; i < NSTRIP; i++) {                                  \
            const float4 q = areg[i];                                       \
            sx[i] += (q.x + q.y) + (q.z + q.w);                             \
            sw[i] += q.x * w4.x + q.y * w4.y + q.z * w4.z + q.w * w4.w;     \
            const uint32_t p0 = pack2h(q.x, q.y), p1 = pack2h(q.z, q.w);    \
            asm volatile("st.shared.v2.b32 [%0], {%1,%2};"                  \
                         :: "r"(asts + aof_ + i * (16 * AROW)), "r"(p0), "r"(p1)); \
        }                                                                   \
        _Pragma("unroll")                                                   \
        for (int j = 0; j < 4; j++)                                         \
            asm volatile("st.shared.v4.b32 [%0], {%1,%2,%3,%4};"            \
                         :: "r"(bsts + bof_ + j * (32 * AROW)), "r"(breg[j].x), \
                            "r"(breg[j].y), "r"(breg[j].z), "r"(breg[j].w));\
    } while (0)

    LOADA(0); LOADB(0);
    SUMS_STS(0, 0);
    __syncthreads();

#pragma unroll 1
    for (int c = 0; c < NCHH; c++) {
        const bool more = (c + 1 < NCHH);
        if (more) { LOADA(c + 1); LOADB(c + 1); }

        const uint32_t aof = (uint32_t)(c & 1) * ABUF;
        const uint32_t bof = (uint32_t)(c & 1) * BBUF;

#pragma unroll
        for (int ks = 0; ks < 4; ks++) {
            uint32_t bfr[4];
            LDSM_X4(bfr[0], bfr[1], bfr[2], bfr[3], blds + bof + ks * 32);
            uint32_t afr[NSTRIP][4];
#pragma unroll
            for (int s = 0; s < NSTRIP; s++)
                LDSM_X4(afr[s][0], afr[s][1], afr[s][2], afr[s][3],
                        alds + aof + ks * 32 + s * (16 * AROW));
#pragma unroll
            for (int s = 0; s < NSTRIP; s++) {
                MMA_F16(acc[s][0][0], acc[s][0][1],
                        afr[s][0], afr[s][1], afr[s][2], afr[s][3],
                        bfr[0], bfr[1]);
                MMA_F16(acc[s][1][0], acc[s][1][1],
                        afr[s][0], afr[s][1], afr[s][2], afr[s][3],
                        bfr[2], bfr[3]);
            }
        }

        if (more) SUMS_STS(c + 1, (c + 1) & 1);
        __syncthreads();
    }

    // ---------------- epilogue: store partials ----------------
    {
        uint32_t* slab = g_xv[kh];
#pragma unroll
        for (int s = 0; s < NSTRIP; s++) {
            const int r0 = mbase + s * 16 + (lane >> 2);
#pragma unroll
            for (int nt = 0; nt < 2; nt++) {
                const int cp = wid * 8 + nt * 4 + (lane & 3);
                slab[(size_t)r0 * 64 + cp]       = acc[s][nt][0];
                slab[(size_t)(r0 + 8) * 64 + cp] = acc[s][nt][1];
            }
        }
    }

#pragma unroll
    for (int i = 0; i < NSTRIP; i++) {
#pragma unroll
        for (int o = 8; o > 0; o >>= 1) {
            sx[i] += __shfl_xor_sync(0xffffffffu, sx[i], o);
            sw[i] += __shfl_xor_sync(0xffffffffu, sw[i], o);
        }
    }
    if ((t & 15) == 0) {
        const int h = t >> 4;
#pragma unroll
        for (int i = 0; i < NSTRIP; i++) {
            const int row = mbase + i * 16 + h;
            g_sxp[kh][row] = sx[i];
            g_swp[kh][row] = sw[i];
        }
    }
}

// ---------------- combine kernel ----------------
// 2048 blocks x 256 thr; warp w handles row m = blockIdx*8 + w.
// Lane reads one uint2 (2 f16x2 pairs) per slab; fp32 add, square, reduce.
__global__ void combine_kernel(const float* __restrict__ bias,
                               float* __restrict__ out)
{
    const int w = threadIdx.x >> 5, lane = threadIdx.x & 31;
    const int m = blockIdx.x * 8 + w;

    const uint2 a = ((const uint2*)g_xv[0])[(size_t)m * 32 + lane];
    const uint2 b = ((const uint2*)g_xv[1])[(size_t)m * 32 + lane];

    const float2 a0 = __half22float2(*reinterpret_cast<const __half2*>(&a.x));
    const float2 a1 = __half22float2(*reinterpret_cast<const __half2*>(&a.y));
    const float2 b0 = __half22float2(*reinterpret_cast<const __half2*>(&b.x));
    const float2 b1 = __half22float2(*reinterpret_cast<const __half2*>(&b.y));

    const float u0 = a0.x + b0.x, v0 = a0.y + b0.y;
    const float u1 = a1.x + b1.x, v1 = a1.y + b1.y;
    float accv = u0 * u0 + v0 * v0 + u1 * u1 + v1 * v1;

#pragma unroll
    for (int o = 16; o > 0; o >>= 1)
        accv += __shfl_xor_sync(0xffffffffu, accv, o);

    if (lane == 0) {
        const float sxv = g_sxp[0][m] + g_sxp[1][m];
        const float swv = g_swp[0][m] + g_swp[1][m];
        out[m] = swv + bias[0] + T1SCALE * accv - 0.5f * sxv * sxv * g_s2;
    }
}

// ---------------- launch ----------------

extern "C" void kernel_launch(void* const* d_in, const int* in_sizes, int n_in,
                              void* d_out, int out_size) {
    (void)in_sizes; (void)n_in; (void)out_size;
    const float* x = (const float*)d_in[0];
    const float* W = (const float*)d_in[1];
    const float* b = (const float*)d_in[2];
    const float* V = (const float*)d_in[3];
    float* out = (float*)d_out;

    cudaFuncSetAttribute(fm_main, cudaFuncAttributeMaxDynamicSharedMemorySize, SMEM_TOTAL);

    prep_kernel<<<256, 256>>>(V);
    s2a_kernel<<<16, 256>>>();
    s2b_kernel<<<1, 128>>>();
    fm_main<<<GRID, 256, SMEM_TOTAL>>>(x, W);
    combine_kernel<<<MROWS / 8, 256>>>(b, out);
}

// round 16
// speedup vs baseline: 1.1566x; 1.1237x over previous
#include <cuda_runtime.h>
#include <cuda_fp16.h>
#include <stdint.h>

// out[m] = x[m]·W + b + 0.5*||x[m]V||^2 - 0.5*(sum_i x[m,i])^2 * ||V.sum(0)||^2
// x: (16384,4096) f32, W: (1,4096) f32, b: (1,) f32, V: (4096,128) f32, out f32.
// GEMM fp16 (V pre-scaled 4096), f16 acc; side sums exact fp32.
// SPLIT-K grid 294 (147 row-blocks x 2 K-halves), 2 CTAs/SM.
// Warp layout 2 m-halves x 4 n-quads: cuts A-LDSM duplication 8->4
// (L1TEX was the measured bottleneck: 78.8% vs tensor 39.6%).

#define MROWS 16384
#define KDIM  4096
#define NDIM  128
#define KC    64
#define NCHH  32                   // chunks per K-half
#define CTAROWS 112
#define GRID  294
#define AROW  144                  // padded smem row stride (bytes)
#define ABUF  (CTAROWS * AROW)     // 16128
#define BBUF  (128 * AROW)         // 18432
#define SMEM_TOTAL (2 * ABUF + 2 * BBUF)   // 69120 -> 2 CTAs = 138240 < 227KB

#define VSCALE 4096.0f
#define T1SCALE (0.5f / (VSCALE * VSCALE))

__device__ __half g_Vt[(size_t)64 * NDIM * KC];    // chunk-major [c][n][kk], fp16 of 4096*V^T
__device__ float g_spart[256 * NDIM];
__device__ float g_sp2[16 * NDIM];
__device__ float g_s2;
__device__ uint32_t g_xv[2][(size_t)MROWS * 64];   // f16x2 col-pairs, per K-half
__device__ float g_sxp[2][MROWS];
__device__ float g_swp[2][MROWS];

// ---------------- helpers ----------------

static __device__ __forceinline__ uint32_t smem_u32(const void* p) {
    uint32_t r;
    asm("{ .reg .u64 t; cvta.to.shared.u64 t, %1; cvt.u32.u64 %0, t; }"
        : "=r"(r) : "l"(p));
    return r;
}

static __device__ __forceinline__ uint32_t pack2h(float lo, float hi) {
    __half2 h = __floats2half2_rn(lo, hi);
    return *reinterpret_cast<uint32_t*>(&h);
}

#define MMA_F16(d0, d1, a0, a1, a2, a3, b0, b1)                            \
    asm volatile(                                                          \
        "mma.sync.aligned.m16n8k16.row.col.f16.f16.f16.f16 "               \
        "{%0,%1}, {%2,%3,%4,%5}, {%6,%7}, {%0,%1};"                        \
        : "+r"(d0), "+r"(d1)                                               \
        : "r"(a0), "r"(a1), "r"(a2), "r"(a3), "r"(b0), "r"(b1))

#define LDSM_X4(r0, r1, r2, r3, addr)                                      \
    asm volatile("ldmatrix.sync.aligned.m8n8.x4.shared.b16 "               \
                 "{%0,%1,%2,%3}, [%4];"                                    \
                 : "=r"(r0), "=r"(r1), "=r"(r2), "=r"(r3) : "r"(addr))

// ---------------- prep kernels ----------------

__global__ void prep_kernel(const float* __restrict__ V) {
    __shared__ __align__(16) __half sm[128 * 24];
    __shared__ float ps[256];
    const int t = threadIdx.x;
    const int b = blockIdx.x;
    const int k0 = b * 16;
    const int n = t & 127;
    const int half_ = t >> 7;

    float partial = 0.f;
#pragma unroll
    for (int i = 0; i < 8; i++) {
        int kk = 2 * i + half_;
        float v = V[(size_t)(k0 + kk) * NDIM + n];
        partial += v;
        sm[n * 24 + kk] = __float2half_rn(v * VSCALE);
    }
    ps[t] = partial;
    __syncthreads();
    if (t < 128) g_spart[b * 128 + t] = ps[t] + ps[t + 128];

    const int r = t >> 1, part = t & 1;
    const uint4* src = (const uint4*)((const char*)sm + r * 48 + part * 16);
    uint4 u0 = src[0];
    uint4* dst = (uint4*)((char*)g_Vt + (size_t)(b >> 2) * 16384 + r * 128
                          + (b & 3) * 32 + part * 16);
    dst[0] = u0;
}

__global__ void s2a_kernel() {
    __shared__ float sh[256];
    const int t = threadIdx.x;
    const int n = t & 127, part = t >> 7;
    const int b0 = blockIdx.x * 16 + part * 8;
    float s = 0.f;
#pragma unroll
    for (int j = 0; j < 8; j++) s += g_spart[(b0 + j) * 128 + n];
    sh[t] = s;
    __syncthreads();
    if (t < 128) g_sp2[blockIdx.x * 128 + t] = sh[t] + sh[t + 128];
}

__global__ void s2b_kernel() {
    __shared__ float sq[128];
    const int t = threadIdx.x;
    float s = 0.f;
#pragma unroll
    for (int j = 0; j < 16; j++) s += g_sp2[j * 128 + t];
    sq[t] = s * s;
    __syncthreads();
    for (int o = 64; o > 0; o >>= 1) {
        if (t < o) sq[t] += sq[t + o];
        __syncthreads();
    }
    if (t == 0) g_s2 = sq[0];
}

// ---------------- main kernel (split-K half) ----------------
// blockIdx = rb*2 + kh. CTA: 112 rows x 128 cols x K 2048 (32 chunks).
// 8 warps = 2 m-halves (strips 0-3 / 4-6) x 4 n-quads (n32).
// Per SMSP: warps w and w+4 = both halves of one n-quad -> 28 MMAs/ks balanced.

__global__ void __launch_bounds__(256, 2) fm_main(
    const float* __restrict__ x, const float* __restrict__ W)
{
    extern __shared__ __align__(16) char smem[];

    const int t = threadIdx.x;
    const int wid = t >> 5, lane = t & 31;
    const int nq = wid & 3;        // n32 quad
    const int mh = wid >> 2;       // m-half: 0 -> strips 0-3, 1 -> strips 4-6
    const int rb = blockIdx.x >> 1;
    const int kh = blockIdx.x & 1;
    int mbase = rb * CTAROWS;
    if (mbase > MROWS - CTAROWS) mbase = MROWS - CTAROWS;  // overlap; dup writes identical

    const uint32_t sAu = smem_u32(smem);
    const uint32_t sBu = sAu + 2 * ABUF;

    const char* xb = (const char*)x + ((size_t)(mbase + (t >> 4)) << 14)
                   + (size_t)kh * 8192 + (t & 15) * 16;
    const char* vb = (const char*)g_Vt + (size_t)kh * NCHH * 16384 + (size_t)t * 16;
    const float4* wp = (const float4*)W + kh * 512 + (t & 15);

    const uint32_t asts = sAu + (t >> 4) * AROW + (t & 15) * 8;
    const uint32_t bsts = sBu + (t >> 3) * AROW + (t & 7) * 16;

    // ldmatrix bases
    // A: row = mh*64 + strip*16 + (lane&15), k-half by lane>>4
    const uint32_t alds = sAu + (uint32_t)(mh * 64 + (lane & 15)) * AROW
                        + (lane >> 4) * 16;
    // B: row = nq*32 + (lane>>4)*8 + (lane&7) (+16 for second LDSM), k-half (lane>>3)&1
    const uint32_t blds = sBu + (uint32_t)(nq * 32 + (lane >> 4) * 8 + (lane & 7)) * AROW
                        + ((lane >> 3) & 1) * 16;

    // acc[strip][nt][2] (f16x2 pairs); mh1 uses strips 0-2 only
    uint32_t acc[4][4][2];
#pragma unroll
    for (int s = 0; s < 4; s++)
#pragma unroll
        for (int j = 0; j < 4; j++) { acc[s][j][0] = 0u; acc[s][j][1] = 0u; }

    float sx[7], sw[7];
#pragma unroll
    for (int i = 0; i < 7; i++) { sx[i] = 0.f; sw[i] = 0.f; }

    float4 areg[7];
    uint4  breg[4];

#define LOADA(c) do {                                                       \
        _Pragma("unroll")                                                   \
        for (int i = 0; i < 7; i++)                                         \
            areg[i] = *(const float4*)(xb + ((size_t)i << 18) + (c) * 256); \
    } while (0)

#define LOADB(c) do {                                                       \
        _Pragma("unroll")                                                   \
        for (int j = 0; j < 4; j++)                                         \
            breg[j] = *(const uint4*)(vb + (size_t)(c) * 16384 + j * 4096); \
    } while (0)

#define SUMS_STS(c, buf) do {                                               \
        const float4 w4 = wp[(c) * 16];                                     \
        const uint32_t aof_ = (uint32_t)(buf) * ABUF;                       \
        const uint32_t bof_ = (uint32_t)(buf) * BBUF;                       \
        _Pragma("unroll")                                                   \
        for (int i = 0; i < 7; i++) {                                       \
            const float4 q = areg[i];                                       \
            sx[i] += (q.x + q.y) + (q.z + q.w);                             \
            sw[i] += q.x * w4.x + q.y * w4.y + q.z * w4.z + q.w * w4.w;     \
            const uint32_t p0 = pack2h(q.x, q.y), p1 = pack2h(q.z, q.w);    \
            asm volatile("st.shared.v2.b32 [%0], {%1,%2};"                  \
                         :: "r"(asts + aof_ + i * (16 * AROW)), "r"(p0), "r"(p1)); \
        }                                                                   \
        _Pragma("unroll")                                                   \
        for (int j = 0; j < 4; j++)                                         \
            asm volatile("st.shared.v4.b32 [%0], {%1,%2,%3,%4};"            \
                         :: "r"(bsts + bof_ + j * (32 * AROW)), "r"(breg[j].x), \
                            "r"(breg[j].y), "r"(breg[j].z), "r"(breg[j].w));\
    } while (0)

    // one chunk of MMAs: NST strips for this m-half
#define MMA_CHUNK(NST, aof, bof) do {                                       \
        _Pragma("unroll")                                                   \
        for (int ks = 0; ks < 4; ks++) {                                    \
            uint32_t bfr[8];                                                \
            LDSM_X4(bfr[0], bfr[1], bfr[2], bfr[3],                         \
                    blds + (bof) + ks * 32);                                \
            LDSM_X4(bfr[4], bfr[5], bfr[6], bfr[7],                         \
                    blds + (bof) + ks * 32 + 16 * AROW);                    \
            uint32_t afr[NST][4];                                           \
            _Pragma("unroll")                                               \
            for (int s = 0; s < NST; s++)                                   \
                LDSM_X4(afr[s][0], afr[s][1], afr[s][2], afr[s][3],         \
                        alds + (aof) + ks * 32 + s * (16 * AROW));          \
            _Pragma("unroll")                                               \
            for (int s = 0; s < NST; s++)                                   \
                _Pragma("unroll")                                           \
                for (int nt = 0; nt < 4; nt++)                              \
                    MMA_F16(acc[s][nt][0], acc[s][nt][1],                   \
                            afr[s][0], afr[s][1], afr[s][2], afr[s][3],     \
                            bfr[nt * 2], bfr[nt * 2 + 1]);                  \
        }                                                                   \
    } while (0)

    LOADA(0); LOADB(0);
    SUMS_STS(0, 0);
    __syncthreads();

#pragma unroll 1
    for (int c = 0; c < NCHH; c++) {
        const bool more = (c + 1 < NCHH);
        if (more) { LOADA(c + 1); LOADB(c + 1); }

        const uint32_t aof = (uint32_t)(c & 1) * ABUF;
        const uint32_t bof = (uint32_t)(c & 1) * BBUF;

        if (mh == 0) MMA_CHUNK(4, aof, bof);
        else         MMA_CHUNK(3, aof, bof);

        if (more) SUMS_STS(c + 1, (c + 1) & 1);
        __syncthreads();
    }

    // ---------------- epilogue: store f16 partials to slab ----------------
    // warp (mh,nq): strips gs = mh*4+s, cols [nq*32, nq*32+32) = colpairs nq*16+nt*4+(lane&3)
    {
        uint32_t* slab = g_xv[kh];
        const int nst = mh ? 3 : 4;
#pragma unroll
        for (int s = 0; s < 4; s++) {
            if (s >= nst) break;
            const int r0 = mbase + (mh * 4 + s) * 16 + (lane >> 2);
#pragma unroll
            for (int nt = 0; nt < 4; nt++) {
                const int cp = nq * 16 + nt * 4 + (lane & 3);
                slab[(size_t)r0 * 64 + cp]       = acc[s][nt][0];
                slab[(size_t)(r0 + 8) * 64 + cp] = acc[s][nt][1];
            }
        }
    }

    // side sums: reduce over 16 threads sharing each row, store halves
#pragma unroll
    for (int i = 0; i < 7; i++) {
#pragma unroll
        for (int o = 8; o > 0; o >>= 1) {
            sx[i] += __shfl_xor_sync(0xffffffffu, sx[i], o);
            sw[i] += __shfl_xor_sync(0xffffffffu, sw[i], o);
        }
    }
    if ((t & 15) == 0) {
        const int h = t >> 4;
#pragma unroll
        for (int i = 0; i < 7; i++) {
            const int row = mbase + i * 16 + h;
            g_sxp[kh][row] = sx[i];
            g_swp[kh][row] = sw[i];
        }
    }
}

// ---------------- combine kernel ----------------
__global__ void combine_kernel(const float* __restrict__ bias,
                               float* __restrict__ out)
{
    const int w = threadIdx.x >> 5, lane = threadIdx.x & 31;
    const int m = blockIdx.x * 8 + w;

    const uint2 a = ((const uint2*)g_xv[0])[(size_t)m * 32 + lane];
    const uint2 b = ((const uint2*)g_xv[1])[(size_t)m * 32 + lane];

    const float2 a0 = __half22float2(*reinterpret_cast<const __half2*>(&a.x));
    const float2 a1 = __half22float2(*reinterpret_cast<const __half2*>(&a.y));
    const float2 b0 = __half22float2(*reinterpret_cast<const __half2*>(&b.x));
    const float2 b1 = __half22float2(*reinterpret_cast<const __half2*>(&b.y));

    const float u0 = a0.x + b0.x, v0 = a0.y + b0.y;
    const float u1 = a1.x + b1.x, v1 = a1.y + b1.y;
    float accv = u0 * u0 + v0 * v0 + u1 * u1 + v1 * v1;

#pragma unroll
    for (int o = 16; o > 0; o >>= 1)
        accv += __shfl_xor_sync(0xffffffffu, accv, o);

    if (lane == 0) {
        const float sxv = g_sxp[0][m] + g_sxp[1][m];
        const float swv = g_swp[0][m] + g_swp[1][m];
        out[m] = swv + bias[0] + T1SCALE * accv - 0.5f * sxv * sxv * g_s2;
    }
}

// ---------------- launch ----------------

extern "C" void kernel_launch(void* const* d_in, const int* in_sizes, int n_in,
                              void* d_out, int out_size) {
    (void)in_sizes; (void)n_in; (void)out_size;
    const float* x = (const float*)d_in[0];
    const float* W = (const float*)d_in[1];
    const float* b = (const float*)d_in[2];
    const float* V = (const float*)d_in[3];
    float* out = (float*)d_out;

    cudaFuncSetAttribute(fm_main, cudaFuncAttributeMaxDynamicSharedMemorySize, SMEM_TOTAL);

    prep_kernel<<<256, 256>>>(V);
    s2a_kernel<<<16, 256>>>();
    s2b_kernel<<<1, 128>>>();
    fm_main<<<GRID, 256, SMEM_TOTAL>>>(x, W);
    combine_kernel<<<MROWS / 8, 256>>>(b, out);
}